// round 2
// baseline (speedup 1.0000x reference)
#include <cuda_runtime.h>
#include <math.h>

// Problem constants
#define PB 32
#define PL 256
#define PD 256
#define PH 256
#define PE 8
#define PNL 4
#define PK 4
#define NSEQ (PB*PE)          // 256 sequences
#define MROWS (PB*PE*PL)      // 65536 GEMM rows

// Scratch (static device memory; no allocations allowed)
__device__ float g_ln[PB*PL*PD];          // 8MB
__device__ float g_conv[PB*PL*PD];        // 8MB
__device__ float g_pre[MROWS*PH];         // 64MB
__device__ float g_ys[MROWS*PH];          // 64MB
__device__ float g_whhT[PNL*PH*PH];       // 1MB  (W_hh transposed: [l][f][h])

// ---------------------------------------------------------------------------
// Packed f32x2 helpers (B300 dual-issue fp32 path; only reachable via PTX)
// ---------------------------------------------------------------------------
__device__ __forceinline__ unsigned long long pk2(float lo, float hi) {
    unsigned long long r;
    asm("mov.b64 %0, {%1,%2};" : "=l"(r) : "f"(lo), "f"(hi));
    return r;
}
__device__ __forceinline__ float2 upk2(unsigned long long v) {
    float2 r;
    asm("mov.b64 {%0,%1}, %2;" : "=f"(r.x), "=f"(r.y) : "l"(v));
    return r;
}
#define FMA2(d, a, b) asm("fma.rn.f32x2 %0, %1, %2, %0;" : "+l"(d) : "l"(a), "l"(b))

// ---------------------------------------------------------------------------
// LayerNorm: one block per token (B*L), 256 threads
// ---------------------------------------------------------------------------
__global__ __launch_bounds__(256) void ln_kernel(
    const float* __restrict__ x, const float* __restrict__ g,
    const float* __restrict__ bb, float* __restrict__ out)
{
    int tok = blockIdx.x;
    int t = threadIdx.x;
    float v = x[tok*256 + t];
    float s1 = v, s2 = v*v;
    #pragma unroll
    for (int o = 16; o > 0; o >>= 1) {
        s1 += __shfl_xor_sync(0xffffffffu, s1, o);
        s2 += __shfl_xor_sync(0xffffffffu, s2, o);
    }
    __shared__ float a1[8], a2[8];
    int w = t >> 5, ln = t & 31;
    if (ln == 0) { a1[w] = s1; a2[w] = s2; }
    __syncthreads();
    if (w == 0) {
        float b1 = (ln < 8) ? a1[ln] : 0.f;
        float b2 = (ln < 8) ? a2[ln] : 0.f;
        #pragma unroll
        for (int o = 4; o > 0; o >>= 1) {
            b1 += __shfl_xor_sync(0xffffffffu, b1, o);
            b2 += __shfl_xor_sync(0xffffffffu, b2, o);
        }
        if (ln == 0) { a1[0] = b1; a2[0] = b2; }
    }
    __syncthreads();
    float mean = a1[0] * (1.f/256.f);
    float var  = a2[0] * (1.f/256.f) - mean*mean;
    out[tok*256 + t] = (v - mean) * rsqrtf(var + 1e-5f) * g[t] + bb[t];
}

// ---------------------------------------------------------------------------
// Depthwise causal conv1d (K=4, left pad 3): one block per token
// ---------------------------------------------------------------------------
__global__ __launch_bounds__(256) void conv_kernel(
    const float* __restrict__ ln, const float* __restrict__ w,
    const float* __restrict__ cb, float* __restrict__ out)
{
    int tok = blockIdx.x;
    int d = threadIdx.x;
    int b = tok >> 8, l = tok & 255;
    float acc = cb[d];
    #pragma unroll
    for (int k = 0; k < PK; k++) {
        int ls = l - 3 + k;
        if (ls >= 0) acc += ln[(b*256 + ls)*256 + d] * w[d*PK + k];
    }
    out[tok*256 + d] = acc;
}

// ---------------------------------------------------------------------------
// Transpose W_hh -> W_hh^T per layer: whhT[l][f][h] = whh[l][h][f]
// ---------------------------------------------------------------------------
__global__ __launch_bounds__(256) void transpose_whh(
    const float* __restrict__ whh, float* __restrict__ whhT)
{
    int idx = blockIdx.x*256 + threadIdx.x;   // NL*256*256 total
    int l = idx >> 16;
    int f = (idx >> 8) & 255;
    int h = idx & 255;
    whhT[idx] = whh[(l*256 + h)*256 + f];
}

// ---------------------------------------------------------------------------
// Input projection GEMM (double-buffered smem pipeline):
//   pre[m,h] = (sum_f X[m,f]*r[e,f]*W[h,f]) * s[e,h] + bias[h]
// 128x128x16 tile, 256 threads, 8x8 per thread, 2-stage smem pipeline
// ---------------------------------------------------------------------------
#define BM 128
#define BN 128
#define BK 16

__global__ __launch_bounds__(256, 2) void gemm_pre(
    const float* __restrict__ X, const float* __restrict__ Wl,
    const float* __restrict__ rl, const float* __restrict__ sl,
    const float* __restrict__ bl, float* __restrict__ out, int layer0)
{
    __shared__ float As[2][BK][BM+4];
    __shared__ float Bs[2][BK][BN+4];
    int m0 = blockIdx.y * BM;
    int n0 = blockIdx.x * BN;
    int tid = threadIdx.x;
    int tm0 = (tid >> 4) * 8;
    int tn0 = (tid & 15) * 8;

    int rowL = tid >> 2;            // 0..63
    int kq   = (tid & 3) * 4;       // 0,4,8,12

    // Per-thread global row pointers for its two load rows (rowL, rowL+64)
    const float* xrow[2]; const float* rrow[2]; const float* wrow[2];
    #pragma unroll
    for (int i = 0; i < 2; i++) {
        int row = rowL + i*64;
        int m = m0 + row;
        int e = (m >> 8) & 7;
        if (layer0) {
            int b = m >> 11, l = m & 255;
            xrow[i] = X + (size_t)(b*256 + l)*256;
        } else {
            xrow[i] = X + (size_t)m*256;
        }
        rrow[i] = rl + e*256;
        wrow[i] = Wl + (size_t)(n0 + row)*256;
    }

    float acc[8][8];
    #pragma unroll
    for (int i = 0; i < 8; i++)
        #pragma unroll
        for (int j = 0; j < 8; j++) acc[i][j] = 0.f;

    float4 px[2], pr[2], pw[2];
    // Prologue: load tile 0 -> buf 0
    #pragma unroll
    for (int i = 0; i < 2; i++) {
        px[i] = *(const float4*)(xrow[i] + kq);
        pr[i] = *(const float4*)(rrow[i] + kq);
        pw[i] = *(const float4*)(wrow[i] + kq);
    }
    #pragma unroll
    for (int i = 0; i < 2; i++) {
        int row = rowL + i*64;
        As[0][kq  ][row] = px[i].x * pr[i].x;
        As[0][kq+1][row] = px[i].y * pr[i].y;
        As[0][kq+2][row] = px[i].z * pr[i].z;
        As[0][kq+3][row] = px[i].w * pr[i].w;
        Bs[0][kq  ][row] = pw[i].x;
        Bs[0][kq+1][row] = pw[i].y;
        Bs[0][kq+2][row] = pw[i].z;
        Bs[0][kq+3][row] = pw[i].w;
    }
    __syncthreads();

    for (int kt = 0; kt < 16; kt++) {
        int cur = kt & 1;
        // Prefetch next K-tile into registers (hidden under compute)
        if (kt < 15) {
            int koff = (kt+1)*BK + kq;
            #pragma unroll
            for (int i = 0; i < 2; i++) {
                px[i] = *(const float4*)(xrow[i] + koff);
                pr[i] = *(const float4*)(rrow[i] + koff);
                pw[i] = *(const float4*)(wrow[i] + koff);
            }
        }
        // Compute from current buffer
        #pragma unroll
        for (int k = 0; k < BK; k++) {
            float a[8], b[8];
            *(float4*)(a)   = *(const float4*)&As[cur][k][tm0];
            *(float4*)(a+4) = *(const float4*)&As[cur][k][tm0+4];
            *(float4*)(b)   = *(const float4*)&Bs[cur][k][tn0];
            *(float4*)(b+4) = *(const float4*)&Bs[cur][k][tn0+4];
            #pragma unroll
            for (int i = 0; i < 8; i++)
                #pragma unroll
                for (int j = 0; j < 8; j++)
                    acc[i][j] += a[i] * b[j];
        }
        // Stage next tile into the other buffer
        if (kt < 15) {
            int nxt = cur ^ 1;
            #pragma unroll
            for (int i = 0; i < 2; i++) {
                int row = rowL + i*64;
                As[nxt][kq  ][row] = px[i].x * pr[i].x;
                As[nxt][kq+1][row] = px[i].y * pr[i].y;
                As[nxt][kq+2][row] = px[i].z * pr[i].z;
                As[nxt][kq+3][row] = px[i].w * pr[i].w;
                Bs[nxt][kq  ][row] = pw[i].x;
                Bs[nxt][kq+1][row] = pw[i].y;
                Bs[nxt][kq+2][row] = pw[i].z;
                Bs[nxt][kq+3][row] = pw[i].w;
            }
            __syncthreads();
        }
    }

    // Epilogue: * s[e,h] + bias[h]
    #pragma unroll
    for (int i = 0; i < 8; i++) {
        int m = m0 + tm0 + i;
        int e = (m >> 8) & 7;
        #pragma unroll
        for (int j = 0; j < 8; j += 4) {
            int n = n0 + tn0 + j;
            float4 sv = *(const float4*)(sl + e*256 + n);
            float4 bv = *(const float4*)(bl + n);
            float4 o;
            o.x = acc[i][j  ] * sv.x + bv.x;
            o.y = acc[i][j+1] * sv.y + bv.y;
            o.z = acc[i][j+2] * sv.z + bv.z;
            o.w = acc[i][j+3] * sv.w + bv.w;
            *(float4*)(out + (size_t)m*256 + n) = o;
        }
    }
}

// ---------------------------------------------------------------------------
// Recurrence: persistent kernel. 128 blocks x 256 threads, 2 sequences/block.
//   h_t[k] = tanh(pre_t[k] + sum_j h_{t-1}[j] * W_hh[k][j])
// Thread t owns output k=t.
//   K rows [0, 96)   : weights in smem, float4-packed per (group, k)
//   K rows [96, 256) : weights in registers as packed f32x2 pairs
// h double-buffered in smem, per-seq arrays, so ulonglong2 loads give
// ready-paired (h_j, h_{j+1}) operands for fma.rn.f32x2 with zero MOVs.
// ---------------------------------------------------------------------------
#define SRG 24                         // smem weight groups of 4 (96 rows)
#define RRG 40                         // register weight groups of 4 (160 rows)
#define RNN_SMEM (SRG*256*16 + 4096)   // 98304 + h buffers

__global__ __launch_bounds__(256, 1) void rnn_kernel(
    const float* __restrict__ pre, const float* __restrict__ whh,
    const float* __restrict__ whhT,
    float* __restrict__ ys, float* __restrict__ hlast)
{
    extern __shared__ float sm[];
    float* sW = sm;                      // [SRG][256] float4 elements
    float* hA = sm + SRG*256*4;          // [2][256] seq0 h
    float* hB = hA + 512;                // [2][256] seq1 h
    int t = threadIdx.x;
    int q0 = blockIdx.x * 2;

    // Fill smem weights: rows f in [0, 96). sW[(g,k)] = {W[k][4g..4g+3]}
    for (int idx = t; idx < SRG*4*256; idx += 256) {
        int f = idx >> 8, k = idx & 255;
        sW[((f>>2)*256 + k)*4 + (f&3)] = whhT[f*256 + k];
    }
    // Register weights: rows [96, 256), packed pairs
    unsigned long long wreg[RRG*2];
    const float4* wrow = (const float4*)(whh + t*256 + SRG*4);
    #pragma unroll
    for (int i = 0; i < RRG; i++) {
        float4 w = wrow[i];
        wreg[2*i]   = pk2(w.x, w.y);
        wreg[2*i+1] = pk2(w.z, w.w);
    }
    hA[t] = 0.f; hA[256+t] = 0.f; hB[t] = 0.f; hB[256+t] = 0.f;
    __syncthreads();

    const float* pre0 = pre + (size_t)q0 * PL * PH;
    const float* pre1 = pre0 + PL*PH;
    float* ys0 = ys + (size_t)q0 * PL * PH;
    float* ys1 = ys0 + PL*PH;

    float p0n = pre0[t], p1n = pre1[t];
    for (int l = 0; l < PL; l++) {
        float p0 = p0n, p1 = p1n;
        if (l < PL-1) { p0n = pre0[(l+1)*256 + t]; p1n = pre1[(l+1)*256 + t]; }

        // acc pairs: (.lo = even-j partial, .hi = odd-j partial)
        unsigned long long aS0 = pk2(p0, 0.f);
        unsigned long long aS1 = pk2(p1, 0.f);
        unsigned long long aR0 = pk2(0.f, 0.f);
        unsigned long long aR1 = pk2(0.f, 0.f);

        const ulonglong2* h0p = (const ulonglong2*)(hA + (l&1)*256);
        const ulonglong2* h1p = (const ulonglong2*)(hB + (l&1)*256);
        const ulonglong2* sWp = (const ulonglong2*)sW;

        #pragma unroll
        for (int g = 0; g < SRG; g++) {
            ulonglong2 wv = sWp[g*256 + t];     // (w4g,w4g+1),(w4g+2,w4g+3)
            ulonglong2 h0 = h0p[g];             // broadcast
            ulonglong2 h1 = h1p[g];
            FMA2(aS0, h0.x, wv.x); FMA2(aS0, h0.y, wv.y);
            FMA2(aS1, h1.x, wv.x); FMA2(aS1, h1.y, wv.y);
        }
        #pragma unroll
        for (int g = 0; g < RRG; g++) {
            ulonglong2 h0 = h0p[SRG + g];
            ulonglong2 h1 = h1p[SRG + g];
            FMA2(aR0, h0.x, wreg[2*g]); FMA2(aR0, h0.y, wreg[2*g+1]);
            FMA2(aR1, h1.x, wreg[2*g]); FMA2(aR1, h1.y, wreg[2*g+1]);
        }

        float2 s0 = upk2(aS0), r0 = upk2(aR0);
        float2 s1 = upk2(aS1), r1 = upk2(aR1);
        float h0v = tanhf((s0.x + s0.y) + (r0.x + r0.y));
        float h1v = tanhf((s1.x + s1.y) + (r1.x + r1.y));
        ys0[l*256 + t] = h0v;
        ys1[l*256 + t] = h1v;
        int nb = ((l+1) & 1) * 256;
        hA[nb + t] = h0v;
        hB[nb + t] = h1v;
        __syncthreads();
    }

    if (hlast) {
        // last write went to buffer (256&1)=0
        hlast[q0*256 + t]     = hA[t];
        hlast[(q0+1)*256 + t] = hB[t];
    }
}

// ---------------------------------------------------------------------------
extern "C" void kernel_launch(void* const* d_in, const int* in_sizes, int n_in,
                              void* d_out, int out_size)
{
    const float* x      = (const float*)d_in[0];
    const float* conv_w = (const float*)d_in[1];
    const float* conv_b = (const float*)d_in[2];
    const float* ln_g   = (const float*)d_in[3];
    const float* ln_b   = (const float*)d_in[4];
    const float* W_ih   = (const float*)d_in[5];
    const float* W_hh   = (const float*)d_in[6];
    const float* r      = (const float*)d_in[7];
    const float* s      = (const float*)d_in[8];
    const float* b      = (const float*)d_in[9];

    float* out = (float*)d_out;

    static float *p_ln = nullptr, *p_conv = nullptr, *p_pre = nullptr,
                 *p_ys = nullptr, *p_whhT = nullptr;
    static bool attr_done = false;
    if (!p_ln) {
        cudaGetSymbolAddress((void**)&p_ln,   g_ln);
        cudaGetSymbolAddress((void**)&p_conv, g_conv);
        cudaGetSymbolAddress((void**)&p_pre,  g_pre);
        cudaGetSymbolAddress((void**)&p_ys,   g_ys);
        cudaGetSymbolAddress((void**)&p_whhT, g_whhT);
    }
    if (!attr_done) {
        cudaFuncSetAttribute(rnn_kernel,
                             cudaFuncAttributeMaxDynamicSharedMemorySize,
                             RNN_SMEM);
        attr_done = true;
    }

    ln_kernel<<<PB*PL, 256>>>(x, ln_g, ln_b, p_ln);
    conv_kernel<<<PB*PL, 256>>>(p_ln, conv_w, conv_b, p_conv);
    transpose_whh<<<PNL*256, 256>>>(W_hh, p_whhT);

    const size_t hN    = (size_t)MROWS * PH;  // 16,777,216
    const size_t lastN = (size_t)NSEQ * PH;   //     65,536

    float* hdst;
    float* lastdst = nullptr;
    if ((size_t)out_size >= hN) {
        hdst = out;
        if ((size_t)out_size >= hN + lastN) lastdst = out + hN;
    } else {
        hdst = p_ys;
        lastdst = out;
    }

    const float* cur = p_conv;
    int layer0 = 1;
    for (int i = 0; i < PNL; i++) {
        gemm_pre<<<dim3(2, 512), 256>>>(
            cur, W_ih + (size_t)i*PH*PD, r + (size_t)i*PE*PD,
            s + (size_t)i*PE*PH, b + (size_t)i*PH, p_pre, layer0);
        float* ysdst = (i == PNL-1) ? hdst : p_ys;
        float* ldst  = (i == PNL-1) ? lastdst : nullptr;
        rnn_kernel<<<NSEQ/2, 256, RNN_SMEM>>>(
            p_pre, W_hh + (size_t)i*PH*PH, p_whhT + (size_t)i*PH*PH,
            ysdst, ldst);
        cur = ysdst;
        layer0 = 0;
    }
}

// round 3
// speedup vs baseline: 1.6222x; 1.6222x over previous
#include <cuda_runtime.h>
#include <math.h>

// Problem constants
#define PB 32
#define PL 256
#define PD 256
#define PH 256
#define PE 8
#define PNL 4
#define PK 4
#define NSEQ (PB*PE)          // 256 sequences
#define MROWS (PB*PE*PL)      // 65536 GEMM rows

// Scratch (static device memory; no allocations allowed)
__device__ float g_ln[PB*PL*PD];          // 8MB
__device__ float g_conv[PB*PL*PD];        // 8MB
__device__ float g_pre[MROWS*PH];         // 64MB
__device__ float g_ys[MROWS*PH];          // 64MB
__device__ float g_whhT[PNL*PH*PH];       // 1MB  (W_hh transposed: [l][f][h])
__device__ float g_dummy[256];

// ---------------------------------------------------------------------------
// LayerNorm: one block per token (B*L), 256 threads
// ---------------------------------------------------------------------------
__global__ __launch_bounds__(256) void ln_kernel(
    const float* __restrict__ x, const float* __restrict__ g,
    const float* __restrict__ bb, float* __restrict__ out)
{
    int tok = blockIdx.x;
    int t = threadIdx.x;
    float v = x[tok*256 + t];
    float s1 = v, s2 = v*v;
    #pragma unroll
    for (int o = 16; o > 0; o >>= 1) {
        s1 += __shfl_xor_sync(0xffffffffu, s1, o);
        s2 += __shfl_xor_sync(0xffffffffu, s2, o);
    }
    __shared__ float a1[8], a2[8];
    int w = t >> 5, ln = t & 31;
    if (ln == 0) { a1[w] = s1; a2[w] = s2; }
    __syncthreads();
    if (w == 0) {
        float b1 = (ln < 8) ? a1[ln] : 0.f;
        float b2 = (ln < 8) ? a2[ln] : 0.f;
        #pragma unroll
        for (int o = 4; o > 0; o >>= 1) {
            b1 += __shfl_xor_sync(0xffffffffu, b1, o);
            b2 += __shfl_xor_sync(0xffffffffu, b2, o);
        }
        if (ln == 0) { a1[0] = b1; a2[0] = b2; }
    }
    __syncthreads();
    float mean = a1[0] * (1.f/256.f);
    float var  = a2[0] * (1.f/256.f) - mean*mean;
    out[tok*256 + t] = (v - mean) * rsqrtf(var + 1e-5f) * g[t] + bb[t];
}

// ---------------------------------------------------------------------------
// Depthwise causal conv1d (K=4, left pad 3): one block per token
// ---------------------------------------------------------------------------
__global__ __launch_bounds__(256) void conv_kernel(
    const float* __restrict__ ln, const float* __restrict__ w,
    const float* __restrict__ cb, float* __restrict__ out)
{
    int tok = blockIdx.x;
    int d = threadIdx.x;
    int b = tok >> 8, l = tok & 255;
    float acc = cb[d];
    #pragma unroll
    for (int k = 0; k < PK; k++) {
        int ls = l - 3 + k;
        if (ls >= 0) acc += ln[(b*256 + ls)*256 + d] * w[d*PK + k];
    }
    out[tok*256 + d] = acc;
}

// Dummy kernel: shifts launch ordinal so ncu (-s 5 -c 1) captures the rnn.
__global__ void dummy_kernel(float* p) { p[threadIdx.x] = 0.f; }

// ---------------------------------------------------------------------------
// Transpose W_hh -> W_hh^T per layer: whhT[l][f][h] = whh[l][h][f]
// ---------------------------------------------------------------------------
__global__ __launch_bounds__(256) void transpose_whh(
    const float* __restrict__ whh, float* __restrict__ whhT)
{
    int idx = blockIdx.x*256 + threadIdx.x;   // NL*256*256 total
    int l = idx >> 16;
    int f = (idx >> 8) & 255;
    int h = idx & 255;
    whhT[idx] = whh[(l*256 + h)*256 + f];
}

// ---------------------------------------------------------------------------
// Input projection GEMM (R0 version — known 204us):
//   pre[m,h] = (sum_f X[m,f]*r[e,f]*W[h,f]) * s[e,h] + bias[h]
// 128x128x16 tile, 256 threads, 8x8 per thread
// ---------------------------------------------------------------------------
#define BM 128
#define BN 128
#define BK 16

__global__ __launch_bounds__(256) void gemm_pre(
    const float* __restrict__ X, const float* __restrict__ Wl,
    const float* __restrict__ rl, const float* __restrict__ sl,
    const float* __restrict__ bl, float* __restrict__ out, int layer0)
{
    __shared__ float As[BK][BM+4];
    __shared__ float Bs[BK][BN+4];
    int m0 = blockIdx.y * BM;
    int n0 = blockIdx.x * BN;
    int tid = threadIdx.x;
    int tm0 = (tid >> 4) * 8;
    int tn0 = (tid & 15) * 8;
    float acc[8][8];
    #pragma unroll
    for (int i = 0; i < 8; i++)
        #pragma unroll
        for (int j = 0; j < 8; j++) acc[i][j] = 0.f;

    for (int k0 = 0; k0 < 256; k0 += BK) {
        #pragma unroll
        for (int v = tid; v < 512; v += 256) {
            int row = v >> 2;
            int kq  = (v & 3) * 4;
            int m = m0 + row;
            int e = (m >> 8) & 7;
            const float* xrow;
            if (layer0) {
                int b = m >> 11;
                int l = m & 255;
                xrow = X + (size_t)(b*256 + l) * 256;
            } else {
                xrow = X + (size_t)m * 256;
            }
            float4 xv = *(const float4*)(xrow + k0 + kq);
            float4 rv = *(const float4*)(rl + e*256 + k0 + kq);
            As[kq  ][row] = xv.x * rv.x;
            As[kq+1][row] = xv.y * rv.y;
            As[kq+2][row] = xv.z * rv.z;
            As[kq+3][row] = xv.w * rv.w;
            int n = n0 + row;
            float4 wv = *(const float4*)(Wl + (size_t)n*256 + k0 + kq);
            Bs[kq  ][row] = wv.x;
            Bs[kq+1][row] = wv.y;
            Bs[kq+2][row] = wv.z;
            Bs[kq+3][row] = wv.w;
        }
        __syncthreads();
        #pragma unroll
        for (int k = 0; k < BK; k++) {
            float a[8], b[8];
            *(float4*)(a)   = *(const float4*)&As[k][tm0];
            *(float4*)(a+4) = *(const float4*)&As[k][tm0+4];
            *(float4*)(b)   = *(const float4*)&Bs[k][tn0];
            *(float4*)(b+4) = *(const float4*)&Bs[k][tn0+4];
            #pragma unroll
            for (int i = 0; i < 8; i++)
                #pragma unroll
                for (int j = 0; j < 8; j++)
                    acc[i][j] += a[i] * b[j];
        }
        __syncthreads();
    }

    #pragma unroll
    for (int i = 0; i < 8; i++) {
        int m = m0 + tm0 + i;
        int e = (m >> 8) & 7;
        #pragma unroll
        for (int j = 0; j < 8; j += 4) {
            int n = n0 + tn0 + j;
            float4 sv = *(const float4*)(sl + e*256 + n);
            float4 bv = *(const float4*)(bl + n);
            float4 o;
            o.x = acc[i][j  ] * sv.x + bv.x;
            o.y = acc[i][j+1] * sv.y + bv.y;
            o.z = acc[i][j+2] * sv.z + bv.z;
            o.w = acc[i][j+3] * sv.w + bv.w;
            *(float4*)(out + (size_t)m*256 + n) = o;
        }
    }
}

// ---------------------------------------------------------------------------
// Recurrence: persistent kernel. 128 blocks x 256 threads, 2 sequences/block.
//   h_t[k] = tanh(pre_t[k] + sum_j h_{t-1}[j] * W_hh[k][j])
// Thread t owns output k=t. Scalar FFMA, 8 independent accumulator chains.
//   j rows [0, 192)  : weights in smem as float4[group][k] (1 LDS.128 / 4 rows)
//   j rows [192, 256): weights in registers (16 float4 = 64 regs)
// h double-buffered in smem; ONE barrier per step.
// ---------------------------------------------------------------------------
#define SGR 48                          // smem groups of 4 rows (192 rows)
#define RGR 16                          // register groups of 4 rows (64 rows)
#define RNN_SMEM (SGR*256*16 + 4096)    // 196608 + h buffers = 200704

__global__ __launch_bounds__(256, 1) void rnn_kernel(
    const float* __restrict__ pre, const float* __restrict__ whh,
    const float* __restrict__ whhT,
    float* __restrict__ ys, float* __restrict__ hlast)
{
    extern __shared__ float sm[];
    float4* sW4 = (float4*)sm;            // [SGR*256]
    float*  hA  = sm + SGR*256*4;         // [2][256] seq0 h (double-buffered)
    float*  hB  = hA + 512;               // [2][256] seq1 h
    int t = threadIdx.x;
    int q0 = blockIdx.x * 2;

    // Fill smem weights: rows f in [0,192). sW4[g*256+k] = W[k][4g..4g+3]
    for (int idx = t; idx < SGR*4*256; idx += 256) {
        int f = idx >> 8, k = idx & 255;
        sm[((f>>2)*256 + k)*4 + (f&3)] = whhT[f*256 + k];
    }
    // Register weights: rows [192,256): wr[i] = W[t][192+4i .. 195+4i]
    float4 wr[RGR];
    const float4* wrow = (const float4*)(whh + (size_t)t*256 + SGR*4);
    #pragma unroll
    for (int i = 0; i < RGR; i++) wr[i] = wrow[i];

    hA[t] = 0.f; hA[256+t] = 0.f; hB[t] = 0.f; hB[256+t] = 0.f;
    __syncthreads();

    const float* pre0 = pre + (size_t)q0 * PL * PH;
    const float* pre1 = pre0 + PL*PH;
    float* ys0 = ys + (size_t)q0 * PL * PH;
    float* ys1 = ys0 + PL*PH;

    float p0n = pre0[t], p1n = pre1[t];
    for (int l = 0; l < PL; l++) {
        float p0 = p0n, p1 = p1n;
        if (l < PL-1) { p0n = pre0[(l+1)*256 + t]; p1n = pre1[(l+1)*256 + t]; }

        const float4* h0p = (const float4*)(hA + (l&1)*256);
        const float4* h1p = (const float4*)(hB + (l&1)*256);

        // 8 independent accumulator chains (4 per sequence)
        float a0 = p0, a1 = 0.f, a2 = 0.f, a3 = 0.f;
        float b0 = p1, b1 = 0.f, b2 = 0.f, b3 = 0.f;

        #pragma unroll
        for (int g = 0; g < SGR; g++) {
            float4 wv = sW4[g*256 + t];
            float4 h0 = h0p[g];                 // smem broadcast
            float4 h1 = h1p[g];
            a0 += wv.x*h0.x; a1 += wv.y*h0.y; a2 += wv.z*h0.z; a3 += wv.w*h0.w;
            b0 += wv.x*h1.x; b1 += wv.y*h1.y; b2 += wv.z*h1.z; b3 += wv.w*h1.w;
        }
        #pragma unroll
        for (int g = 0; g < RGR; g++) {
            float4 wv = wr[g];
            float4 h0 = h0p[SGR + g];
            float4 h1 = h1p[SGR + g];
            a0 += wv.x*h0.x; a1 += wv.y*h0.y; a2 += wv.z*h0.z; a3 += wv.w*h0.w;
            b0 += wv.x*h1.x; b1 += wv.y*h1.y; b2 += wv.z*h1.z; b3 += wv.w*h1.w;
        }

        float h0v = tanhf((a0 + a1) + (a2 + a3));
        float h1v = tanhf((b0 + b1) + (b2 + b3));
        ys0[l*256 + t] = h0v;
        ys1[l*256 + t] = h1v;
        int nb = ((l+1) & 1) * 256;
        hA[nb + t] = h0v;
        hB[nb + t] = h1v;
        __syncthreads();
    }

    if (hlast) {
        // step 255 wrote buffer (256&1)=0
        hlast[q0*256 + t]     = hA[t];
        hlast[(q0+1)*256 + t] = hB[t];
    }
}

// ---------------------------------------------------------------------------
extern "C" void kernel_launch(void* const* d_in, const int* in_sizes, int n_in,
                              void* d_out, int out_size)
{
    const float* x      = (const float*)d_in[0];
    const float* conv_w = (const float*)d_in[1];
    const float* conv_b = (const float*)d_in[2];
    const float* ln_g   = (const float*)d_in[3];
    const float* ln_b   = (const float*)d_in[4];
    const float* W_ih   = (const float*)d_in[5];
    const float* W_hh   = (const float*)d_in[6];
    const float* r      = (const float*)d_in[7];
    const float* s      = (const float*)d_in[8];
    const float* b      = (const float*)d_in[9];

    float* out = (float*)d_out;

    static float *p_ln = nullptr, *p_conv = nullptr, *p_pre = nullptr,
                 *p_ys = nullptr, *p_whhT = nullptr, *p_dummy = nullptr;
    static bool attr_done = false;
    if (!p_ln) {
        cudaGetSymbolAddress((void**)&p_ln,    g_ln);
        cudaGetSymbolAddress((void**)&p_conv,  g_conv);
        cudaGetSymbolAddress((void**)&p_pre,   g_pre);
        cudaGetSymbolAddress((void**)&p_ys,    g_ys);
        cudaGetSymbolAddress((void**)&p_whhT,  g_whhT);
        cudaGetSymbolAddress((void**)&p_dummy, g_dummy);
    }
    if (!attr_done) {
        cudaFuncSetAttribute(rnn_kernel,
                             cudaFuncAttributeMaxDynamicSharedMemorySize,
                             RNN_SMEM);
        attr_done = true;
    }

    // Launch order matters for ncu (-s 5 -c 1 captures the 6th launch = rnn)
    ln_kernel<<<PB*PL, 256>>>(x, ln_g, ln_b, p_ln);                 // 1
    conv_kernel<<<PB*PL, 256>>>(p_ln, conv_w, conv_b, p_conv);      // 2
    dummy_kernel<<<1, 256>>>(p_dummy);                              // 3
    transpose_whh<<<PNL*256, 256>>>(W_hh, p_whhT);                  // 4

    const size_t hN    = (size_t)MROWS * PH;  // 16,777,216
    const size_t lastN = (size_t)NSEQ * PH;   //     65,536

    float* hdst;
    float* lastdst = nullptr;
    if ((size_t)out_size >= hN) {
        hdst = out;
        if ((size_t)out_size >= hN + lastN) lastdst = out + hN;
    } else {
        hdst = p_ys;
        lastdst = out;
    }

    const float* cur = p_conv;
    int layer0 = 1;
    for (int i = 0; i < PNL; i++) {
        gemm_pre<<<dim3(2, 512), 256>>>(                            // 5, 7, ...
            cur, W_ih + (size_t)i*PH*PD, r + (size_t)i*PE*PD,
            s + (size_t)i*PE*PH, b + (size_t)i*PH, p_pre, layer0);
        float* ysdst = (i == PNL-1) ? hdst : p_ys;
        float* ldst  = (i == PNL-1) ? lastdst : nullptr;
        rnn_kernel<<<NSEQ/2, 256, RNN_SMEM>>>(                      // 6 = profiled
            p_pre, W_hh + (size_t)i*PH*PH, p_whhT + (size_t)i*PH*PH,
            ysdst, ldst);
        cur = ysdst;
        layer0 = 0;
    }
}

// round 4
// speedup vs baseline: 1.7816x; 1.0982x over previous
#include <cuda_runtime.h>
#include <math.h>

// Problem constants
#define PB 32
#define PL 256
#define PD 256
#define PH 256
#define PE 8
#define PNL 4
#define PK 4
#define NSEQ (PB*PE)          // 256 sequences
#define MROWS (PB*PE*PL)      // 65536 GEMM rows

// Scratch (static device memory; no allocations allowed)
__device__ float g_ln[PB*PL*PD];          // 8MB
__device__ float g_conv[PB*PL*PD];        // 8MB
__device__ float g_pre[MROWS*PH];         // 64MB
__device__ float g_ys[MROWS*PH];          // 64MB
__device__ float g_whhT[PNL*PH*PH];       // 1MB  (W_hh transposed: [l][f][h])

// ---------------------------------------------------------------------------
// LayerNorm: one block per token (B*L), 256 threads
// ---------------------------------------------------------------------------
__global__ __launch_bounds__(256) void ln_kernel(
    const float* __restrict__ x, const float* __restrict__ g,
    const float* __restrict__ bb, float* __restrict__ out)
{
    int tok = blockIdx.x;
    int t = threadIdx.x;
    float v = x[tok*256 + t];
    float s1 = v, s2 = v*v;
    #pragma unroll
    for (int o = 16; o > 0; o >>= 1) {
        s1 += __shfl_xor_sync(0xffffffffu, s1, o);
        s2 += __shfl_xor_sync(0xffffffffu, s2, o);
    }
    __shared__ float a1[8], a2[8];
    int w = t >> 5, ln = t & 31;
    if (ln == 0) { a1[w] = s1; a2[w] = s2; }
    __syncthreads();
    if (w == 0) {
        float b1 = (ln < 8) ? a1[ln] : 0.f;
        float b2 = (ln < 8) ? a2[ln] : 0.f;
        #pragma unroll
        for (int o = 4; o > 0; o >>= 1) {
            b1 += __shfl_xor_sync(0xffffffffu, b1, o);
            b2 += __shfl_xor_sync(0xffffffffu, b2, o);
        }
        if (ln == 0) { a1[0] = b1; a2[0] = b2; }
    }
    __syncthreads();
    float mean = a1[0] * (1.f/256.f);
    float var  = a2[0] * (1.f/256.f) - mean*mean;
    out[tok*256 + t] = (v - mean) * rsqrtf(var + 1e-5f) * g[t] + bb[t];
}

// ---------------------------------------------------------------------------
// Fused: depthwise causal conv1d (blocks [0, PB*PL)) + W_hh transpose
// (blocks [PB*PL, PB*PL + PNL*256)). Keeps rnn at our-launch #4 for ncu.
// ---------------------------------------------------------------------------
__global__ __launch_bounds__(256) void conv_transpose_kernel(
    const float* __restrict__ ln, const float* __restrict__ w,
    const float* __restrict__ cb, float* __restrict__ out,
    const float* __restrict__ whh, float* __restrict__ whhT)
{
    if (blockIdx.x < PB*PL) {
        int tok = blockIdx.x;
        int d = threadIdx.x;
        int b = tok >> 8, l = tok & 255;
        float acc = cb[d];
        #pragma unroll
        for (int k = 0; k < PK; k++) {
            int ls = l - 3 + k;
            if (ls >= 0) acc += ln[(b*256 + ls)*256 + d] * w[d*PK + k];
        }
        out[tok*256 + d] = acc;
    } else {
        int idx = (blockIdx.x - PB*PL)*256 + threadIdx.x;  // NL*256*256 total
        int l = idx >> 16;
        int f = (idx >> 8) & 255;
        int h = idx & 255;
        whhT[idx] = whh[(l*256 + h)*256 + f];
    }
}

// ---------------------------------------------------------------------------
// Input projection GEMM (known-good 204us version):
//   pre[m,h] = (sum_f X[m,f]*r[e,f]*W[h,f]) * s[e,h] + bias[h]
// 128x128x16 tile, 256 threads, 8x8 per thread
// ---------------------------------------------------------------------------
#define BM 128
#define BN 128
#define BK 16

__global__ __launch_bounds__(256) void gemm_pre(
    const float* __restrict__ X, const float* __restrict__ Wl,
    const float* __restrict__ rl, const float* __restrict__ sl,
    const float* __restrict__ bl, float* __restrict__ out, int layer0)
{
    __shared__ float As[BK][BM+4];
    __shared__ float Bs[BK][BN+4];
    int m0 = blockIdx.y * BM;
    int n0 = blockIdx.x * BN;
    int tid = threadIdx.x;
    int tm0 = (tid >> 4) * 8;
    int tn0 = (tid & 15) * 8;
    float acc[8][8];
    #pragma unroll
    for (int i = 0; i < 8; i++)
        #pragma unroll
        for (int j = 0; j < 8; j++) acc[i][j] = 0.f;

    for (int k0 = 0; k0 < 256; k0 += BK) {
        #pragma unroll
        for (int v = tid; v < 512; v += 256) {
            int row = v >> 2;
            int kq  = (v & 3) * 4;
            int m = m0 + row;
            int e = (m >> 8) & 7;
            const float* xrow;
            if (layer0) {
                int b = m >> 11;
                int l = m & 255;
                xrow = X + (size_t)(b*256 + l) * 256;
            } else {
                xrow = X + (size_t)m * 256;
            }
            float4 xv = *(const float4*)(xrow + k0 + kq);
            float4 rv = *(const float4*)(rl + e*256 + k0 + kq);
            As[kq  ][row] = xv.x * rv.x;
            As[kq+1][row] = xv.y * rv.y;
            As[kq+2][row] = xv.z * rv.z;
            As[kq+3][row] = xv.w * rv.w;
            int n = n0 + row;
            float4 wv = *(const float4*)(Wl + (size_t)n*256 + k0 + kq);
            Bs[kq  ][row] = wv.x;
            Bs[kq+1][row] = wv.y;
            Bs[kq+2][row] = wv.z;
            Bs[kq+3][row] = wv.w;
        }
        __syncthreads();
        #pragma unroll
        for (int k = 0; k < BK; k++) {
            float a[8], b[8];
            *(float4*)(a)   = *(const float4*)&As[k][tm0];
            *(float4*)(a+4) = *(const float4*)&As[k][tm0+4];
            *(float4*)(b)   = *(const float4*)&Bs[k][tn0];
            *(float4*)(b+4) = *(const float4*)&Bs[k][tn0+4];
            #pragma unroll
            for (int i = 0; i < 8; i++)
                #pragma unroll
                for (int j = 0; j < 8; j++)
                    acc[i][j] += a[i] * b[j];
        }
        __syncthreads();
    }

    #pragma unroll
    for (int i = 0; i < 8; i++) {
        int m = m0 + tm0 + i;
        int e = (m >> 8) & 7;
        #pragma unroll
        for (int j = 0; j < 8; j += 4) {
            int n = n0 + tn0 + j;
            float4 sv = *(const float4*)(sl + e*256 + n);
            float4 bv = *(const float4*)(bl + n);
            float4 o;
            o.x = acc[i][j  ] * sv.x + bv.x;
            o.y = acc[i][j+1] * sv.y + bv.y;
            o.z = acc[i][j+2] * sv.z + bv.z;
            o.w = acc[i][j+3] * sv.w + bv.w;
            *(float4*)(out + (size_t)m*256 + n) = o;
        }
    }
}

// ---------------------------------------------------------------------------
// Recurrence: persistent kernel. 128 blocks x 256 threads, 2 sequences/block.
//   h_t[k] = tanh(pre_t[k] + sum_j h_{t-1}[j] * W_hh[k][j])
// Thread t owns output k=t. Scalar FFMA, 8 independent accumulator chains.
//   j rows [0, 128)  : weights in smem as float4[group][k] (1 LDS.128 / 4 rows)
//   j rows [128, 256): weights in registers (32 float4 = 128 regs, invariant)
// h double-buffered in smem; ONE barrier per step.
// LDS wavefronts/warp/step: 32*4 (weights) + 64*2 (h broadcast) = 256
//   << FMA issue 2048 cyc -> FMA-bound.
// ---------------------------------------------------------------------------
#define SGR 32                          // smem groups of 4 rows (128 rows)
#define RGR 32                          // register groups of 4 rows (128 rows)
#define RNN_SMEM (SGR*256*16 + 4096)    // 131072 + h buffers = 135168

__global__ __launch_bounds__(256, 1) void rnn_kernel(
    const float* __restrict__ pre, const float* __restrict__ whh,
    const float* __restrict__ whhT,
    float* __restrict__ ys, float* __restrict__ hlast)
{
    extern __shared__ float sm[];
    float4* sW4 = (float4*)sm;            // [SGR*256]
    float*  hA  = sm + SGR*256*4;         // [2][256] seq0 h (double-buffered)
    float*  hB  = hA + 512;               // [2][256] seq1 h
    int t = threadIdx.x;
    int q0 = blockIdx.x * 2;

    // Fill smem weights: rows f in [0,128). sW4[g*256+k] = W[k][4g..4g+3]
    #pragma unroll 4
    for (int idx = t; idx < SGR*4*256; idx += 256) {
        int f = idx >> 8, k = idx & 255;
        sm[((f>>2)*256 + k)*4 + (f&3)] = whhT[f*256 + k];
    }
    // Register weights: rows [128,256): wr[i] = W[t][128+4i .. 131+4i]
    float4 wr[RGR];
    const float4* wrow = (const float4*)(whh + (size_t)t*256 + SGR*4);
    #pragma unroll
    for (int i = 0; i < RGR; i++) wr[i] = wrow[i];

    hA[t] = 0.f; hA[256+t] = 0.f; hB[t] = 0.f; hB[256+t] = 0.f;
    __syncthreads();

    const float* pre0 = pre + (size_t)q0 * PL * PH;
    const float* pre1 = pre0 + PL*PH;
    float* ys0 = ys + (size_t)q0 * PL * PH;
    float* ys1 = ys0 + PL*PH;

    float p0n = pre0[t], p1n = pre1[t];
    for (int l = 0; l < PL; l++) {
        float p0 = p0n, p1 = p1n;
        if (l < PL-1) { p0n = pre0[(l+1)*256 + t]; p1n = pre1[(l+1)*256 + t]; }

        const float4* h0p = (const float4*)(hA + (l&1)*256);
        const float4* h1p = (const float4*)(hB + (l&1)*256);

        // 8 independent accumulator chains (4 per sequence)
        float a0 = p0, a1 = 0.f, a2 = 0.f, a3 = 0.f;
        float b0 = p1, b1 = 0.f, b2 = 0.f, b3 = 0.f;

        #pragma unroll
        for (int g = 0; g < SGR; g++) {
            float4 wv = sW4[g*256 + t];
            float4 h0 = h0p[g];                 // smem broadcast
            float4 h1 = h1p[g];
            a0 += wv.x*h0.x; a1 += wv.y*h0.y; a2 += wv.z*h0.z; a3 += wv.w*h0.w;
            b0 += wv.x*h1.x; b1 += wv.y*h1.y; b2 += wv.z*h1.z; b3 += wv.w*h1.w;
        }
        #pragma unroll
        for (int g = 0; g < RGR; g++) {
            float4 wv = wr[g];
            float4 h0 = h0p[SGR + g];
            float4 h1 = h1p[SGR + g];
            a0 += wv.x*h0.x; a1 += wv.y*h0.y; a2 += wv.z*h0.z; a3 += wv.w*h0.w;
            b0 += wv.x*h1.x; b1 += wv.y*h1.y; b2 += wv.z*h1.z; b3 += wv.w*h1.w;
        }

        float h0v = tanhf((a0 + a1) + (a2 + a3));
        float h1v = tanhf((b0 + b1) + (b2 + b3));
        ys0[l*256 + t] = h0v;
        ys1[l*256 + t] = h1v;
        int nb = ((l+1) & 1) * 256;
        hA[nb + t] = h0v;
        hB[nb + t] = h1v;
        __syncthreads();
    }

    if (hlast) {
        // step 255 wrote buffer (256&1)=0
        hlast[q0*256 + t]     = hA[t];
        hlast[(q0+1)*256 + t] = hB[t];
    }
}

// ---------------------------------------------------------------------------
extern "C" void kernel_launch(void* const* d_in, const int* in_sizes, int n_in,
                              void* d_out, int out_size)
{
    const float* x      = (const float*)d_in[0];
    const float* conv_w = (const float*)d_in[1];
    const float* conv_b = (const float*)d_in[2];
    const float* ln_g   = (const float*)d_in[3];
    const float* ln_b   = (const float*)d_in[4];
    const float* W_ih   = (const float*)d_in[5];
    const float* W_hh   = (const float*)d_in[6];
    const float* r      = (const float*)d_in[7];
    const float* s      = (const float*)d_in[8];
    const float* b      = (const float*)d_in[9];

    float* out = (float*)d_out;

    static float *p_ln = nullptr, *p_conv = nullptr, *p_pre = nullptr,
                 *p_ys = nullptr, *p_whhT = nullptr;
    static bool attr_done = false;
    if (!p_ln) {
        cudaGetSymbolAddress((void**)&p_ln,    g_ln);
        cudaGetSymbolAddress((void**)&p_conv,  g_conv);
        cudaGetSymbolAddress((void**)&p_pre,   g_pre);
        cudaGetSymbolAddress((void**)&p_ys,    g_ys);
        cudaGetSymbolAddress((void**)&p_whhT,  g_whhT);
    }
    if (!attr_done) {
        cudaFuncSetAttribute(rnn_kernel,
                             cudaFuncAttributeMaxDynamicSharedMemorySize,
                             RNN_SMEM);
        attr_done = true;
    }

    // Our launch #4 is the rnn: harness pre-issues 2 launches, ncu -s 5 -c 1
    // captures overall launch #6 = our #4.
    ln_kernel<<<PB*PL, 256>>>(x, ln_g, ln_b, p_ln);                        // 1
    conv_transpose_kernel<<<PB*PL + PNL*256, 256>>>(                       // 2
        p_ln, conv_w, conv_b, p_conv, W_hh, p_whhT);

    const size_t hN    = (size_t)MROWS * PH;  // 16,777,216
    const size_t lastN = (size_t)NSEQ * PH;   //     65,536

    float* hdst;
    float* lastdst = nullptr;
    if ((size_t)out_size >= hN) {
        hdst = out;
        if ((size_t)out_size >= hN + lastN) lastdst = out + hN;
    } else {
        hdst = p_ys;
        lastdst = out;
    }

    const float* cur = p_conv;
    int layer0 = 1;
    for (int i = 0; i < PNL; i++) {
        gemm_pre<<<dim3(2, 512), 256>>>(                                   // 3
            cur, W_ih + (size_t)i*PH*PD, r + (size_t)i*PE*PD,
            s + (size_t)i*PE*PH, b + (size_t)i*PH, p_pre, layer0);
        float* ysdst = (i == PNL-1) ? hdst : p_ys;
        float* ldst  = (i == PNL-1) ? lastdst : nullptr;
        rnn_kernel<<<NSEQ/2, 256, RNN_SMEM>>>(                             // 4 = profiled
            p_pre, W_hh + (size_t)i*PH*PH, p_whhT + (size_t)i*PH*PH,
            ysdst, ldst);
        cur = ysdst;
        layer0 = 0;
    }
}